// round 1
// baseline (speedup 1.0000x reference)
#include <cuda_runtime.h>

#define NN 100000
#define NE 1600000
#define FIN 128
#define FH  64
#define FO  10

// Scratch (device globals — no allocation allowed)
__device__ __align__(16) float g_deg[NN];
__device__ __align__(16) float g_dinv[NN];
__device__ __align__(16) float g_h[NN * FH];    // x @ W1
__device__ __align__(16) float g_agg[NN * FH];  // aggregated layer-1 (pre-relu, incl. b1)
__device__ __align__(16) float g_h2[NN * FO];   // relu(agg) @ W2

__device__ __forceinline__ void red_add_v4(float* p, float4 v) {
    asm volatile("red.global.add.v4.f32 [%0], {%1,%2,%3,%4};"
                 :: "l"(p), "f"(v.x), "f"(v.y), "f"(v.z), "f"(v.w) : "memory");
}
__device__ __forceinline__ void red_add_v2(float* p, float2 v) {
    asm volatile("red.global.add.v2.f32 [%0], {%1,%2};"
                 :: "l"(p), "f"(v.x), "f"(v.y) : "memory");
}

// ---------------- degree / norm ----------------
__global__ void k_deg_init() {
    int i = blockIdx.x * blockDim.x + threadIdx.x;
    if (i < NN) g_deg[i] = 1.0f;  // self-loop
}

__global__ void k_deg_scatter(const int* __restrict__ dst) {
    int e = blockIdx.x * blockDim.x + threadIdx.x;
    if (e < NE) atomicAdd(&g_deg[dst[e]], 1.0f);
}

__global__ void k_dinv() {
    int i = blockIdx.x * blockDim.x + threadIdx.x;
    if (i < NN) g_dinv[i] = rsqrtf(g_deg[i]);
}

// ---------------- GEMM1: h = x @ W1  (100000x128 @ 128x64) ----------------
// Block: 256 threads; tile 128 rows x 64 cols. Thread: 4 rows x 8 cols.
__global__ void __launch_bounds__(256) k_gemm1(const float* __restrict__ x,
                                               const float* __restrict__ W1) {
    __shared__ float Ws[FIN * FH];  // 32KB
    const int tid = threadIdx.x;

    // cooperative load W1 (8192 floats) as float4
    {
        float4* Ws4 = reinterpret_cast<float4*>(Ws);
        const float4* W14 = reinterpret_cast<const float4*>(W1);
#pragma unroll
        for (int i = 0; i < 8; i++) Ws4[tid + 256 * i] = W14[tid + 256 * i];
    }
    __syncthreads();

    const int tx = tid & 7;   // col group: cols tx*8 .. tx*8+7
    const int ty = tid >> 3;  // row group: 4 rows each
    const int row0 = blockIdx.x * 128 + ty * 4;

    // clamp row indices (OOB rows computed but not stored)
    const float* xr0 = x + (size_t)min(row0 + 0, NN - 1) * FIN;
    const float* xr1 = x + (size_t)min(row0 + 1, NN - 1) * FIN;
    const float* xr2 = x + (size_t)min(row0 + 2, NN - 1) * FIN;
    const float* xr3 = x + (size_t)min(row0 + 3, NN - 1) * FIN;

    float acc[4][8];
#pragma unroll
    for (int r = 0; r < 4; r++)
#pragma unroll
        for (int c = 0; c < 8; c++) acc[r][c] = 0.0f;

    const float4* Ws4 = reinterpret_cast<const float4*>(Ws);

#pragma unroll 4
    for (int k = 0; k < FIN; k++) {
        float4 wa = Ws4[k * 16 + tx * 2];
        float4 wb = Ws4[k * 16 + tx * 2 + 1];
        float xv0 = __ldg(&xr0[k]);
        float xv1 = __ldg(&xr1[k]);
        float xv2 = __ldg(&xr2[k]);
        float xv3 = __ldg(&xr3[k]);
        float xv[4] = {xv0, xv1, xv2, xv3};
#pragma unroll
        for (int r = 0; r < 4; r++) {
            acc[r][0] = fmaf(xv[r], wa.x, acc[r][0]);
            acc[r][1] = fmaf(xv[r], wa.y, acc[r][1]);
            acc[r][2] = fmaf(xv[r], wa.z, acc[r][2]);
            acc[r][3] = fmaf(xv[r], wa.w, acc[r][3]);
            acc[r][4] = fmaf(xv[r], wb.x, acc[r][4]);
            acc[r][5] = fmaf(xv[r], wb.y, acc[r][5]);
            acc[r][6] = fmaf(xv[r], wb.z, acc[r][6]);
            acc[r][7] = fmaf(xv[r], wb.w, acc[r][7]);
        }
    }

    float4* h4 = reinterpret_cast<float4*>(g_h);
#pragma unroll
    for (int r = 0; r < 4; r++) {
        int row = row0 + r;
        if (row < NN) {
            float4 o0 = make_float4(acc[r][0], acc[r][1], acc[r][2], acc[r][3]);
            float4 o1 = make_float4(acc[r][4], acc[r][5], acc[r][6], acc[r][7]);
            h4[row * 16 + tx * 2]     = o0;
            h4[row * 16 + tx * 2 + 1] = o1;
        }
    }
}

// ---------------- agg init: self-loop + bias ----------------
// agg[n][:] = h[n][:] * dinv[n]^2 + b1[:]
__global__ void k_agg_init(const float* __restrict__ b1) {
    int idx = blockIdx.x * blockDim.x + threadIdx.x;  // over NN*16 float4's
    if (idx >= NN * 16) return;
    int n = idx >> 4;
    int q = idx & 15;
    float di = g_dinv[n];
    float nrm = di * di;
    float4 h = reinterpret_cast<const float4*>(g_h)[idx];
    float4 b = reinterpret_cast<const float4*>(b1)[q];
    float4 o;
    o.x = fmaf(h.x, nrm, b.x);
    o.y = fmaf(h.y, nrm, b.y);
    o.z = fmaf(h.z, nrm, b.z);
    o.w = fmaf(h.w, nrm, b.w);
    reinterpret_cast<float4*>(g_agg)[idx] = o;
}

// ---------------- scatter1: agg[dst] += h[src] * norm ----------------
// 16 lanes per edge, one float4 each.
__global__ void k_scatter1(const int* __restrict__ src, const int* __restrict__ dst) {
    int idx = blockIdx.x * blockDim.x + threadIdx.x;  // over NE*16
    if (idx >= NE * 16) return;
    int e = idx >> 4;
    int q = idx & 15;
    int s = src[e];
    int d = dst[e];
    float nrm = g_dinv[s] * g_dinv[d];
    float4 v = reinterpret_cast<const float4*>(g_h)[s * 16 + q];
    v.x *= nrm; v.y *= nrm; v.z *= nrm; v.w *= nrm;
    red_add_v4(&g_agg[d * FH + q * 4], v);
}

// ---------------- GEMM2: h2 = relu(agg) @ W2  (100000x64 @ 64x10) ----------------
__global__ void __launch_bounds__(256) k_gemm2(const float* __restrict__ W2) {
    __shared__ float Ws[FH * FO];  // 640 floats
    for (int i = threadIdx.x; i < FH * FO; i += blockDim.x) Ws[i] = W2[i];
    __syncthreads();

    int n = blockIdx.x * blockDim.x + threadIdx.x;
    if (n >= NN) return;

    float acc[FO];
#pragma unroll
    for (int j = 0; j < FO; j++) acc[j] = 0.0f;

    const float4* a4 = reinterpret_cast<const float4*>(g_agg + n * FH);
#pragma unroll
    for (int k4 = 0; k4 < 16; k4++) {
        float4 a = a4[k4];
        float av[4] = {fmaxf(a.x, 0.f), fmaxf(a.y, 0.f), fmaxf(a.z, 0.f), fmaxf(a.w, 0.f)};
#pragma unroll
        for (int kk = 0; kk < 4; kk++) {
            int k = k4 * 4 + kk;
#pragma unroll
            for (int j = 0; j < FO; j++) acc[j] = fmaf(av[kk], Ws[k * FO + j], acc[j]);
        }
    }

    float2* o2 = reinterpret_cast<float2*>(g_h2 + n * FO);
#pragma unroll
    for (int c = 0; c < 5; c++) o2[c] = make_float2(acc[c * 2], acc[c * 2 + 1]);
}

// ---------------- out init: self-loop + bias ----------------
__global__ void k_out_init(const float* __restrict__ b2, float* __restrict__ out) {
    int idx = blockIdx.x * blockDim.x + threadIdx.x;  // over NN*10
    if (idx >= NN * FO) return;
    int n = idx / FO;
    int j = idx - n * FO;
    float di = g_dinv[n];
    out[idx] = fmaf(g_h2[idx], di * di, b2[j]);
}

// ---------------- scatter2: out[dst] += h2[src] * norm ----------------
__global__ void k_scatter2(const int* __restrict__ src, const int* __restrict__ dst,
                           float* __restrict__ out) {
    int e = blockIdx.x * blockDim.x + threadIdx.x;
    if (e >= NE) return;
    int s = src[e];
    int d = dst[e];
    float nrm = g_dinv[s] * g_dinv[d];
    const float2* hp = reinterpret_cast<const float2*>(g_h2 + s * FO);
    float* op = out + d * FO;
#pragma unroll
    for (int c = 0; c < 5; c++) {
        float2 v = hp[c];
        v.x *= nrm; v.y *= nrm;
        red_add_v2(op + c * 2, v);
    }
}

extern "C" void kernel_launch(void* const* d_in, const int* in_sizes, int n_in,
                              void* d_out, int out_size) {
    const float* x  = (const float*)d_in[0];
    const int*   ei = (const int*)d_in[1];
    const float* W1 = (const float*)d_in[2];
    const float* b1 = (const float*)d_in[3];
    const float* W2 = (const float*)d_in[4];
    const float* b2 = (const float*)d_in[5];
    float* out = (float*)d_out;

    const int* src = ei;       // edge_index[0]
    const int* dst = ei + NE;  // edge_index[1]

    k_deg_init<<<(NN + 255) / 256, 256>>>();
    k_deg_scatter<<<(NE + 255) / 256, 256>>>(dst);
    k_dinv<<<(NN + 255) / 256, 256>>>();
    k_gemm1<<<(NN + 127) / 128, 256>>>(x, W1);
    k_agg_init<<<(NN * 16 + 255) / 256, 256>>>(b1);
    k_scatter1<<<(NE * 16 + 255) / 256, 256>>>(src, dst);
    k_gemm2<<<(NN + 255) / 256, 256>>>(W2);
    k_out_init<<<(NN * FO + 255) / 256, 256>>>(b2, out);
    k_scatter2<<<(NE + 255) / 256, 256>>>(src, dst, out);
}

// round 2
// speedup vs baseline: 1.2495x; 1.2495x over previous
#include <cuda_runtime.h>

#define NN 100000
#define NE 1600000
#define FIN 128
#define FH  64
#define FO  10

typedef unsigned long long u64;

// Scratch (device globals — no allocation allowed)
__device__ __align__(16) float g_deg[NN];
__device__ __align__(16) float g_dinv[NN];
__device__ __align__(16) float g_norm[NE];
__device__ __align__(16) float g_h[NN * FH];    // x @ W1
__device__ __align__(16) float g_agg[NN * FH];  // aggregated layer-1 (incl. self-loop + b1)
__device__ __align__(16) float g_h2[NN * FO];   // relu(agg) @ W2

__device__ __forceinline__ void red_add_v4(float* p, float4 v) {
    asm volatile("red.global.add.v4.f32 [%0], {%1,%2,%3,%4};"
                 :: "l"(p), "f"(v.x), "f"(v.y), "f"(v.z), "f"(v.w) : "memory");
}
__device__ __forceinline__ void red_add_v2(float* p, float2 v) {
    asm volatile("red.global.add.v2.f32 [%0], {%1,%2};"
                 :: "l"(p), "f"(v.x), "f"(v.y) : "memory");
}

// ---- packed f32x2 helpers ----
__device__ __forceinline__ u64 dup2(float v) {
    u64 d;
    asm("mov.b64 %0, {%1,%1};" : "=l"(d) : "f"(v));
    return d;
}
__device__ __forceinline__ void ffma2(u64& d, u64 a, u64 b) {
    asm("fma.rn.f32x2 %0, %1, %2, %0;" : "+l"(d) : "l"(a), "l"(b));
}
__device__ __forceinline__ float2 unpack2(u64 d) {
    float lo, hi;
    asm("mov.b64 {%0,%1}, %2;" : "=f"(lo), "=f"(hi) : "l"(d));
    return make_float2(lo, hi);
}

// ---------------- degree / norm ----------------
__global__ void k_deg_init() {
    int i = blockIdx.x * blockDim.x + threadIdx.x;
    if (i < NN) g_deg[i] = 1.0f;  // self-loop
}

__global__ void k_deg_scatter(const int* __restrict__ dst) {
    int e = blockIdx.x * blockDim.x + threadIdx.x;
    if (e < NE) atomicAdd(&g_deg[dst[e]], 1.0f);
}

__global__ void k_dinv() {
    int i = blockIdx.x * blockDim.x + threadIdx.x;
    if (i < NN) g_dinv[i] = rsqrtf(g_deg[i]);
}

__global__ void k_norm(const int* __restrict__ src, const int* __restrict__ dst) {
    int e = blockIdx.x * blockDim.x + threadIdx.x;
    if (e < NE) g_norm[e] = g_dinv[src[e]] * g_dinv[dst[e]];
}

// ---------------- GEMM1 fused: h = x@W1 ; agg = h*dinv^2 + b1 ----------------
// Block: 256 threads, 256 rows x 64 cols. Thread: 8 rows (stride-32) x 8 cols.
// K chunked by 64; x chunk staged in smem (pitch 17 float4, conflict-free).
// FMA via packed fma.rn.f32x2 (col pairs).
#define XS_F4 (256 * 17)           // 4352 float4 = 69632 B
#define GEMM1_SMEM (XS_F4 * 16 + 64 * 64 * 4)  // + W chunk 16384 B = 86016 B

__global__ void __launch_bounds__(256, 2) k_gemm1(const float* __restrict__ x,
                                                  const float* __restrict__ W1,
                                                  const float* __restrict__ b1) {
    extern __shared__ float4 sm4[];
    float4* xs4 = sm4;                         // [256][17]
    float*  Ws  = (float*)(sm4 + XS_F4);       // [64][64]
    __shared__ float b1s[FH];

    const int tid = threadIdx.x;
    const int c  = tid & 7;    // col group (8 cols)
    const int rg = tid >> 3;   // row base (rows rg + 32*i)
    const int row_base = blockIdx.x * 256;

    if (tid < FH) b1s[tid] = b1[tid];

    u64 acc[8][4];
#pragma unroll
    for (int i = 0; i < 8; i++)
#pragma unroll
        for (int p = 0; p < 4; p++) acc[i][p] = 0ull;

    const float4* x4  = reinterpret_cast<const float4*>(x);
    const float4* W14 = reinterpret_cast<const float4*>(W1);
    float4* Ws4 = reinterpret_cast<float4*>(Ws);

    for (int kc = 0; kc < 2; kc++) {
        // ---- stage x chunk: 256 rows x 64 k (16 float4/row) ----
#pragma unroll
        for (int j = 0; j < 16; j++) {
            int f = tid + 256 * j;        // 0..4095
            int row = f >> 4;
            int kq  = f & 15;
            int grow = min(row_base + row, NN - 1);
            xs4[row * 17 + kq] = x4[(size_t)grow * 32 + kc * 16 + kq];
        }
        // ---- stage W chunk: 64 k x 64 cols = 1024 float4 ----
#pragma unroll
        for (int j = 0; j < 4; j++) {
            int f = tid + 256 * j;
            Ws4[f] = W14[kc * 1024 + f];
        }
        __syncthreads();

#define ROWSTEP(i, comp)                                   \
        {                                                  \
            u64 xd = dup2(xq[i].comp);                     \
            ffma2(acc[i][0], xd, wA.x);                    \
            ffma2(acc[i][1], xd, wA.y);                    \
            ffma2(acc[i][2], xd, wB.x);                    \
            ffma2(acc[i][3], xd, wB.y);                    \
        }
#define KSTEP(comp, kk)                                                        \
        {                                                                      \
            const ulonglong2* wr =                                             \
                (const ulonglong2*)(Ws + (k4 * 4 + kk) * 64 + c * 8);          \
            ulonglong2 wA = wr[0];                                             \
            ulonglong2 wB = wr[1];                                             \
            ROWSTEP(0, comp) ROWSTEP(1, comp) ROWSTEP(2, comp) ROWSTEP(3, comp)\
            ROWSTEP(4, comp) ROWSTEP(5, comp) ROWSTEP(6, comp) ROWSTEP(7, comp)\
        }

#pragma unroll 4
        for (int k4 = 0; k4 < 16; k4++) {
            float4 xq[8];
#pragma unroll
            for (int i = 0; i < 8; i++) xq[i] = xs4[(rg + 32 * i) * 17 + k4];
            KSTEP(x, 0)
            KSTEP(y, 1)
            KSTEP(z, 2)
            KSTEP(w, 3)
        }
        __syncthreads();
    }

    // ---- epilogue: write h and agg = h*dinv^2 + b1 ----
    float4* h4 = reinterpret_cast<float4*>(g_h);
    float4* a4 = reinterpret_cast<float4*>(g_agg);
    float4 bv0, bv1;
    {
        const float4* b4 = reinterpret_cast<const float4*>(b1s);
        bv0 = b4[c * 2];
        bv1 = b4[c * 2 + 1];
    }
#pragma unroll
    for (int i = 0; i < 8; i++) {
        int grow = row_base + rg + 32 * i;
        if (grow < NN) {
            float2 p0 = unpack2(acc[i][0]);
            float2 p1 = unpack2(acc[i][1]);
            float2 p2 = unpack2(acc[i][2]);
            float2 p3 = unpack2(acc[i][3]);
            float4 o0 = make_float4(p0.x, p0.y, p1.x, p1.y);
            float4 o1 = make_float4(p2.x, p2.y, p3.x, p3.y);
            h4[grow * 16 + c * 2]     = o0;
            h4[grow * 16 + c * 2 + 1] = o1;
            float di = g_dinv[grow];
            float nrm = di * di;
            float4 ag0, ag1;
            ag0.x = fmaf(o0.x, nrm, bv0.x); ag0.y = fmaf(o0.y, nrm, bv0.y);
            ag0.z = fmaf(o0.z, nrm, bv0.z); ag0.w = fmaf(o0.w, nrm, bv0.w);
            ag1.x = fmaf(o1.x, nrm, bv1.x); ag1.y = fmaf(o1.y, nrm, bv1.y);
            ag1.z = fmaf(o1.z, nrm, bv1.z); ag1.w = fmaf(o1.w, nrm, bv1.w);
            a4[grow * 16 + c * 2]     = ag0;
            a4[grow * 16 + c * 2 + 1] = ag1;
        }
    }
#undef KSTEP
#undef ROWSTEP
}

// ---------------- scatter1: agg[dst] += h[src] * norm ----------------
__global__ void k_scatter1(const int* __restrict__ src, const int* __restrict__ dst) {
    int idx = blockIdx.x * blockDim.x + threadIdx.x;  // over NE*16
    if (idx >= NE * 16) return;
    int e = idx >> 4;
    int q = idx & 15;
    int s = src[e];
    int d = dst[e];
    float nrm = g_norm[e];
    float4 v = reinterpret_cast<const float4*>(g_h)[s * 16 + q];
    v.x *= nrm; v.y *= nrm; v.z *= nrm; v.w *= nrm;
    red_add_v4(&g_agg[d * FH + q * 4], v);
}

// ---------------- GEMM2 fused: h2 = relu(agg)@W2 ; out = h2*dinv^2 + b2 ----------------
__global__ void __launch_bounds__(256) k_gemm2(const float* __restrict__ W2,
                                               const float* __restrict__ b2,
                                               float* __restrict__ out) {
    __shared__ float Ws[FH * FO];
    __shared__ float b2s[FO];
    for (int i = threadIdx.x; i < FH * FO; i += blockDim.x) Ws[i] = W2[i];
    if (threadIdx.x < FO) b2s[threadIdx.x] = b2[threadIdx.x];
    __syncthreads();

    int n = blockIdx.x * blockDim.x + threadIdx.x;
    if (n >= NN) return;

    float acc[FO];
#pragma unroll
    for (int j = 0; j < FO; j++) acc[j] = 0.0f;

    const float4* a4 = reinterpret_cast<const float4*>(g_agg + n * FH);
#pragma unroll
    for (int k4 = 0; k4 < 16; k4++) {
        float4 a = a4[k4];
        float av[4] = {fmaxf(a.x, 0.f), fmaxf(a.y, 0.f), fmaxf(a.z, 0.f), fmaxf(a.w, 0.f)};
#pragma unroll
        for (int kk = 0; kk < 4; kk++) {
            int k = k4 * 4 + kk;
#pragma unroll
            for (int j = 0; j < FO; j++) acc[j] = fmaf(av[kk], Ws[k * FO + j], acc[j]);
        }
    }

    float di = g_dinv[n];
    float nrm = di * di;
    float2* h2p = reinterpret_cast<float2*>(g_h2 + n * FO);
    float2* op  = reinterpret_cast<float2*>(out + n * FO);
#pragma unroll
    for (int p = 0; p < 5; p++) {
        h2p[p] = make_float2(acc[p * 2], acc[p * 2 + 1]);
        op[p]  = make_float2(fmaf(acc[p * 2], nrm, b2s[p * 2]),
                             fmaf(acc[p * 2 + 1], nrm, b2s[p * 2 + 1]));
    }
}

// ---------------- scatter2: out[dst] += h2[src] * norm ----------------
__global__ void k_scatter2(const int* __restrict__ src, const int* __restrict__ dst,
                           float* __restrict__ out) {
    int e = blockIdx.x * blockDim.x + threadIdx.x;
    if (e >= NE) return;
    int s = src[e];
    int d = dst[e];
    float nrm = g_norm[e];
    const float2* hp = reinterpret_cast<const float2*>(g_h2 + s * FO);
    float* op = out + d * FO;
#pragma unroll
    for (int c = 0; c < 5; c++) {
        float2 v = hp[c];
        v.x *= nrm; v.y *= nrm;
        red_add_v2(op + c * 2, v);
    }
}

extern "C" void kernel_launch(void* const* d_in, const int* in_sizes, int n_in,
                              void* d_out, int out_size) {
    const float* x  = (const float*)d_in[0];
    const int*   ei = (const int*)d_in[1];
    const float* W1 = (const float*)d_in[2];
    const float* b1 = (const float*)d_in[3];
    const float* W2 = (const float*)d_in[4];
    const float* b2 = (const float*)d_in[5];
    float* out = (float*)d_out;

    const int* src = ei;       // edge_index[0]
    const int* dst = ei + NE;  // edge_index[1]

    static bool attr_set = false;
    if (!attr_set) {
        cudaFuncSetAttribute(k_gemm1, cudaFuncAttributeMaxDynamicSharedMemorySize,
                             GEMM1_SMEM);
        attr_set = true;
    }

    k_deg_init<<<(NN + 255) / 256, 256>>>();
    k_deg_scatter<<<(NE + 255) / 256, 256>>>(dst);
    k_dinv<<<(NN + 255) / 256, 256>>>();
    k_norm<<<(NE + 255) / 256, 256>>>(src, dst);
    k_gemm1<<<(NN + 255) / 256, 256, GEMM1_SMEM>>>(x, W1, b1);
    k_scatter1<<<(NE * 16 + 255) / 256, 256>>>(src, dst);
    k_gemm2<<<(NN + 255) / 256, 256>>>(W2, b2, out);
    k_scatter2<<<(NE + 255) / 256, 256>>>(src, dst, out);
}

// round 3
// speedup vs baseline: 1.5018x; 1.2019x over previous
#include <cuda_runtime.h>

#define NN 100000
#define NE 1600000
#define FIN 128
#define FH  64
#define FO  10

#define SCAN_BLK 512
#define NSCAN ((NN + SCAN_BLK - 1) / SCAN_BLK)   // 196

typedef unsigned long long u64;

// ---- scratch (device globals; no allocation allowed) ----
__device__ int   g_indeg[NN];
__device__ int   g_off[NN];
__device__ int   g_cursor[NN];
__device__ int   g_offp[NN];
__device__ int   g_bsum[NSCAN];
__device__ int   g_bsumex[NSCAN];
__device__ int   g_csrc[NE];
__device__ float g_dinv[NN];
__device__ __align__(16) float g_hs[NN * FH];    // (x@W1) * dinv[row]
__device__ __align__(16) float g_agg[NN * FH];   // relu(b1 + dinv*(hs[d]+sum hs[src]))
__device__ __align__(16) float g_h2s[NN * 16];   // (agg@W2) * dinv[row], padded stride 16

// ---- packed f32x2 helpers ----
__device__ __forceinline__ u64 dup2(float v) {
    u64 d; asm("mov.b64 %0, {%1,%1};" : "=l"(d) : "f"(v)); return d;
}
__device__ __forceinline__ void ffma2(u64& d, u64 a, u64 b) {
    asm("fma.rn.f32x2 %0, %1, %2, %0;" : "+l"(d) : "l"(a), "l"(b));
}
__device__ __forceinline__ float2 unpack2(u64 d) {
    float lo, hi; asm("mov.b64 {%0,%1}, %2;" : "=f"(lo), "=f"(hi) : "l"(d));
    return make_float2(lo, hi);
}

// ================= degree / dinv =================
__global__ void k_zero() {
    int i = blockIdx.x * blockDim.x + threadIdx.x;
    if (i < NN) g_indeg[i] = 0;
}
__global__ void k_indeg(const int* __restrict__ dst) {
    int e = blockIdx.x * blockDim.x + threadIdx.x;
    if (e < NE) atomicAdd(&g_indeg[dst[e]], 1);
}
__global__ void k_dinv() {
    int i = blockIdx.x * blockDim.x + threadIdx.x;
    if (i < NN) g_dinv[i] = rsqrtf(1.0f + (float)g_indeg[i]);
}

// ================= exclusive scan of g_indeg -> g_off (3 pass) =================
__global__ void __launch_bounds__(SCAN_BLK) k_scan1() {
    int i = blockIdx.x * SCAN_BLK + threadIdx.x;
    int v = (i < NN) ? g_indeg[i] : 0;
    int lane = threadIdx.x & 31, w = threadIdx.x >> 5;
    int s = v;
#pragma unroll
    for (int o = 1; o < 32; o <<= 1) {
        int t = __shfl_up_sync(0xffffffffu, s, o);
        if (lane >= o) s += t;
    }
    __shared__ int wsum[16];
    if (lane == 31) wsum[w] = s;
    __syncthreads();
    if (w == 0) {
        int t = (lane < 16) ? wsum[lane] : 0;
#pragma unroll
        for (int o = 1; o < 16; o <<= 1) {
            int u = __shfl_up_sync(0xffffffffu, t, o);
            if (lane >= o) t += u;
        }
        if (lane < 16) wsum[lane] = t;
    }
    __syncthreads();
    int excl = s - v + ((w > 0) ? wsum[w - 1] : 0);
    if (i < NN) g_offp[i] = excl;
    if (threadIdx.x == 0) g_bsum[blockIdx.x] = wsum[15];
}
__global__ void __launch_bounds__(256) k_scan2() {
    int tid = threadIdx.x;
    int v = (tid < NSCAN) ? g_bsum[tid] : 0;
    int lane = tid & 31, w = tid >> 5;
    int s = v;
#pragma unroll
    for (int o = 1; o < 32; o <<= 1) {
        int t = __shfl_up_sync(0xffffffffu, s, o);
        if (lane >= o) s += t;
    }
    __shared__ int wsum[8];
    if (lane == 31) wsum[w] = s;
    __syncthreads();
    if (w == 0) {
        int t = (lane < 8) ? wsum[lane] : 0;
#pragma unroll
        for (int o = 1; o < 8; o <<= 1) {
            int u = __shfl_up_sync(0xffffffffu, t, o);
            if (lane >= o) t += u;
        }
        if (lane < 8) wsum[lane] = t;
    }
    __syncthreads();
    int incl = s + ((w > 0) ? wsum[w - 1] : 0);
    if (tid < NSCAN) g_bsumex[tid] = incl - v;
}
__global__ void k_scan3() {
    int i = blockIdx.x * blockDim.x + threadIdx.x;
    if (i < NN) {
        int o = g_offp[i] + g_bsumex[i / SCAN_BLK];
        g_off[i] = o;
        g_cursor[i] = o;
    }
}

// ================= CSR positional scatter =================
__global__ void k_edge_pos(const int* __restrict__ src, const int* __restrict__ dst) {
    int e = blockIdx.x * blockDim.x + threadIdx.x;
    if (e < NE) {
        int pos = atomicAdd(&g_cursor[dst[e]], 1);
        g_csrc[pos] = src[e];
    }
}

// ================= GEMM1: hs = (x @ W1) * dinv[row] =================
#define XS_F4 (256 * 17)
#define GEMM1_SMEM (XS_F4 * 16 + 64 * 64 * 4)   // 86016 B

__global__ void __launch_bounds__(256, 2) k_gemm1(const float* __restrict__ x,
                                                  const float* __restrict__ W1) {
    extern __shared__ float4 sm4[];
    float4* xs4 = sm4;                     // [256][17]
    float*  Ws  = (float*)(sm4 + XS_F4);   // [64][64]

    const int tid = threadIdx.x;
    const int c  = tid & 7;
    const int rg = tid >> 3;
    const int row_base = blockIdx.x * 256;

    u64 acc[8][4];
#pragma unroll
    for (int i = 0; i < 8; i++)
#pragma unroll
        for (int p = 0; p < 4; p++) acc[i][p] = 0ull;

    const float4* x4  = reinterpret_cast<const float4*>(x);
    const float4* W14 = reinterpret_cast<const float4*>(W1);
    float4* Ws4 = reinterpret_cast<float4*>(Ws);

    for (int kc = 0; kc < 2; kc++) {
#pragma unroll
        for (int j = 0; j < 16; j++) {
            int f = tid + 256 * j;
            int row = f >> 4;
            int kq  = f & 15;
            int grow = min(row_base + row, NN - 1);
            xs4[row * 17 + kq] = x4[(size_t)grow * 32 + kc * 16 + kq];
        }
#pragma unroll
        for (int j = 0; j < 4; j++) {
            int f = tid + 256 * j;
            Ws4[f] = W14[kc * 1024 + f];
        }
        __syncthreads();

#define ROWSTEP(i, comp)                                   \
        {                                                  \
            u64 xd = dup2(xq[i].comp);                     \
            ffma2(acc[i][0], xd, wA.x);                    \
            ffma2(acc[i][1], xd, wA.y);                    \
            ffma2(acc[i][2], xd, wB.x);                    \
            ffma2(acc[i][3], xd, wB.y);                    \
        }
#define KSTEP(comp, kk)                                                        \
        {                                                                      \
            const ulonglong2* wr =                                             \
                (const ulonglong2*)(Ws + (k4 * 4 + kk) * 64 + c * 8);          \
            ulonglong2 wA = wr[0];                                             \
            ulonglong2 wB = wr[1];                                             \
            ROWSTEP(0, comp) ROWSTEP(1, comp) ROWSTEP(2, comp) ROWSTEP(3, comp)\
            ROWSTEP(4, comp) ROWSTEP(5, comp) ROWSTEP(6, comp) ROWSTEP(7, comp)\
        }

#pragma unroll 4
        for (int k4 = 0; k4 < 16; k4++) {
            float4 xq[8];
#pragma unroll
            for (int i = 0; i < 8; i++) xq[i] = xs4[(rg + 32 * i) * 17 + k4];
            KSTEP(x, 0)
            KSTEP(y, 1)
            KSTEP(z, 2)
            KSTEP(w, 3)
        }
        __syncthreads();
    }

    float4* hs4 = reinterpret_cast<float4*>(g_hs);
#pragma unroll
    for (int i = 0; i < 8; i++) {
        int grow = row_base + rg + 32 * i;
        if (grow < NN) {
            float di = g_dinv[grow];
            float2 p0 = unpack2(acc[i][0]);
            float2 p1 = unpack2(acc[i][1]);
            float2 p2 = unpack2(acc[i][2]);
            float2 p3 = unpack2(acc[i][3]);
            float4 o0 = make_float4(p0.x * di, p0.y * di, p1.x * di, p1.y * di);
            float4 o1 = make_float4(p2.x * di, p2.y * di, p3.x * di, p3.y * di);
            hs4[grow * 16 + c * 2]     = o0;
            hs4[grow * 16 + c * 2 + 1] = o1;
        }
    }
#undef KSTEP
#undef ROWSTEP
}

// ================= agg1: warp-per-node gather-sum =================
// agg[d] = relu(b1 + dinv[d] * (hs[d] + sum_{src in CSR(d)} hs[src]))
__global__ void __launch_bounds__(256) k_agg1(const float* __restrict__ b1) {
    int wg = (blockIdx.x * blockDim.x + threadIdx.x) >> 5;
    if (wg >= NN) return;
    const int d = wg;
    const int lane = threadIdx.x & 31;

    const float2* hs2 = reinterpret_cast<const float2*>(g_hs);
    float2 acc = hs2[(size_t)d * 32 + lane];

    const int beg = g_off[d];
    const int cnt = g_indeg[d];
    for (int base = 0; base < cnt; base += 32) {
        int rem = cnt - base;
        int take = rem < 32 ? rem : 32;
        int s = 0;
        if (lane < take) s = g_csrc[beg + base + lane];
#pragma unroll 4
        for (int j = 0; j < take; j++) {
            int sj = __shfl_sync(0xffffffffu, s, j);
            float2 v = hs2[(size_t)sj * 32 + lane];
            acc.x += v.x;
            acc.y += v.y;
        }
    }

    float di = g_dinv[d];
    float2 b = reinterpret_cast<const float2*>(b1)[lane];
    float2 o;
    o.x = fmaxf(fmaf(acc.x, di, b.x), 0.0f);
    o.y = fmaxf(fmaf(acc.y, di, b.y), 0.0f);
    reinterpret_cast<float2*>(g_agg)[(size_t)d * 32 + lane] = o;
}

// ================= GEMM2: h2s = (agg @ W2) * dinv[row], stride-16 padded ======
__global__ void __launch_bounds__(256) k_gemm2(const float* __restrict__ W2) {
    __shared__ float Ws[FH * FO];
    for (int i = threadIdx.x; i < FH * FO; i += blockDim.x) Ws[i] = W2[i];
    __syncthreads();

    int n = blockIdx.x * blockDim.x + threadIdx.x;
    if (n >= NN) return;

    float acc[FO];
#pragma unroll
    for (int j = 0; j < FO; j++) acc[j] = 0.0f;

    const float4* a4 = reinterpret_cast<const float4*>(g_agg + (size_t)n * FH);
#pragma unroll
    for (int k4 = 0; k4 < 16; k4++) {
        float4 a = a4[k4];
        float av[4] = {a.x, a.y, a.z, a.w};
#pragma unroll
        for (int kk = 0; kk < 4; kk++) {
            int k = k4 * 4 + kk;
#pragma unroll
            for (int j = 0; j < FO; j++) acc[j] = fmaf(av[kk], Ws[k * FO + j], acc[j]);
        }
    }

    float di = g_dinv[n];
    float2* o2 = reinterpret_cast<float2*>(g_h2s + (size_t)n * 16);
#pragma unroll
    for (int p = 0; p < 5; p++)
        o2[p] = make_float2(acc[p * 2] * di, acc[p * 2 + 1] * di);
}

// ================= agg2: warp-per-node gather-sum (10 features) =================
// out[d] = b2 + dinv[d] * (h2s[d] + sum h2s[src])
__global__ void __launch_bounds__(256) k_agg2(const float* __restrict__ b2,
                                              float* __restrict__ out) {
    int wg = (blockIdx.x * blockDim.x + threadIdx.x) >> 5;
    if (wg >= NN) return;
    const int d = wg;
    const int lane = threadIdx.x & 31;

    float acc = 0.0f;
    if (lane < FO) acc = g_h2s[(size_t)d * 16 + lane];

    const int beg = g_off[d];
    const int cnt = g_indeg[d];
    for (int base = 0; base < cnt; base += 32) {
        int rem = cnt - base;
        int take = rem < 32 ? rem : 32;
        int s = 0;
        if (lane < take) s = g_csrc[beg + base + lane];
#pragma unroll 4
        for (int j = 0; j < take; j++) {
            int sj = __shfl_sync(0xffffffffu, s, j);
            if (lane < FO) acc += g_h2s[(size_t)sj * 16 + lane];
        }
    }

    if (lane < FO) {
        float di = g_dinv[d];
        out[(size_t)d * FO + lane] = fmaf(acc, di, b2[lane]);
    }
}

extern "C" void kernel_launch(void* const* d_in, const int* in_sizes, int n_in,
                              void* d_out, int out_size) {
    const float* x  = (const float*)d_in[0];
    const int*   ei = (const int*)d_in[1];
    const float* W1 = (const float*)d_in[2];
    const float* b1 = (const float*)d_in[3];
    const float* W2 = (const float*)d_in[4];
    const float* b2 = (const float*)d_in[5];
    float* out = (float*)d_out;

    const int* src = ei;
    const int* dst = ei + NE;

    static bool attr_set = false;
    if (!attr_set) {
        cudaFuncSetAttribute(k_gemm1, cudaFuncAttributeMaxDynamicSharedMemorySize,
                             GEMM1_SMEM);
        attr_set = true;
    }

    k_zero<<<(NN + 255) / 256, 256>>>();
    k_indeg<<<(NE + 255) / 256, 256>>>(dst);
    k_dinv<<<(NN + 255) / 256, 256>>>();
    k_scan1<<<NSCAN, SCAN_BLK>>>();
    k_scan2<<<1, 256>>>();
    k_scan3<<<(NN + 255) / 256, 256>>>();
    k_edge_pos<<<(NE + 255) / 256, 256>>>(src, dst);
    k_gemm1<<<(NN + 255) / 256, 256, GEMM1_SMEM>>>(x, W1);
    k_agg1<<<(NN * 32 + 255) / 256, 256>>>(b1);
    k_gemm2<<<(NN + 255) / 256, 256>>>(W2);
    k_agg2<<<(NN * 32 + 255) / 256, 256>>>(b2, out);
}

// round 5
// speedup vs baseline: 1.5719x; 1.0467x over previous
#include <cuda_runtime.h>
#include <cuda_fp16.h>

#define NN 100000
#define NE 1600000
#define FIN 128
#define FH  64
#define FO  10

#define SCAN_BLK 512
#define NSCAN ((NN + SCAN_BLK - 1) / SCAN_BLK)   // 196

typedef unsigned long long u64;

// ---- scratch (device globals; no allocation allowed) ----
__device__ int   g_indeg[NN];
__device__ int   g_off[NN];
__device__ int   g_cursor[NN];
__device__ int   g_offp[NN];
__device__ int   g_bsum[NSCAN];
__device__ int   g_bsumex[NSCAN];
__device__ int   g_csrc[NE];
__device__ float g_dinv[NN];
__device__ __align__(16) __half g_hs[NN * FH];   // (x@W1) * dinv[row], fp16
__device__ __align__(16) float  g_agg[NN * FH];  // relu(b1 + dinv*(hs[d]+sum hs[src]))
__device__ __align__(16) float  g_h2s[NN * 16];  // (agg@W2) * dinv[row], padded stride 16

// ---- packed f32x2 helpers ----
__device__ __forceinline__ u64 dup2(float v) {
    u64 d; asm("mov.b64 %0, {%1,%1};" : "=l"(d) : "f"(v)); return d;
}
__device__ __forceinline__ void ffma2(u64& d, u64 a, u64 b) {
    asm("fma.rn.f32x2 %0, %1, %2, %0;" : "+l"(d) : "l"(a), "l"(b));
}
__device__ __forceinline__ float2 unpack2(u64 d) {
    float lo, hi; asm("mov.b64 {%0,%1}, %2;" : "=f"(lo), "=f"(hi) : "l"(d));
    return make_float2(lo, hi);
}
__device__ __forceinline__ unsigned h2_bits(__half2 h) {
    return *reinterpret_cast<unsigned*>(&h);
}

// ================= degree =================
__global__ void k_zero() {
    int i = blockIdx.x * blockDim.x + threadIdx.x;
    if (i < NN) g_indeg[i] = 0;
}
__global__ void k_indeg(const int* __restrict__ dst) {
    int e = blockIdx.x * blockDim.x + threadIdx.x;
    if (e < NE) atomicAdd(&g_indeg[dst[e]], 1);
}

// ================= scan pass 1 (+ dinv fused) =================
__global__ void __launch_bounds__(SCAN_BLK) k_scan1() {
    int i = blockIdx.x * SCAN_BLK + threadIdx.x;
    int v = (i < NN) ? g_indeg[i] : 0;
    if (i < NN) g_dinv[i] = rsqrtf(1.0f + (float)v);
    int lane = threadIdx.x & 31, w = threadIdx.x >> 5;
    int s = v;
#pragma unroll
    for (int o = 1; o < 32; o <<= 1) {
        int t = __shfl_up_sync(0xffffffffu, s, o);
        if (lane >= o) s += t;
    }
    __shared__ int wsum[16];
    if (lane == 31) wsum[w] = s;
    __syncthreads();
    if (w == 0) {
        int t = (lane < 16) ? wsum[lane] : 0;
#pragma unroll
        for (int o = 1; o < 16; o <<= 1) {
            int u = __shfl_up_sync(0xffffffffu, t, o);
            if (lane >= o) t += u;
        }
        if (lane < 16) wsum[lane] = t;
    }
    __syncthreads();
    int excl = s - v + ((w > 0) ? wsum[w - 1] : 0);
    if (i < NN) g_offp[i] = excl;
    if (threadIdx.x == 0) g_bsum[blockIdx.x] = wsum[15];
}
__global__ void __launch_bounds__(256) k_scan2() {
    int tid = threadIdx.x;
    int v = (tid < NSCAN) ? g_bsum[tid] : 0;
    int lane = tid & 31, w = tid >> 5;
    int s = v;
#pragma unroll
    for (int o = 1; o < 32; o <<= 1) {
        int t = __shfl_up_sync(0xffffffffu, s, o);
        if (lane >= o) s += t;
    }
    __shared__ int wsum[8];
    if (lane == 31) wsum[w] = s;
    __syncthreads();
    if (w == 0) {
        int t = (lane < 8) ? wsum[lane] : 0;
#pragma unroll
        for (int o = 1; o < 8; o <<= 1) {
            int u = __shfl_up_sync(0xffffffffu, t, o);
            if (lane >= o) t += u;
        }
        if (lane < 8) wsum[lane] = t;
    }
    __syncthreads();
    int incl = s + ((w > 0) ? wsum[w - 1] : 0);
    if (tid < NSCAN) g_bsumex[tid] = incl - v;
}
__global__ void k_scan3() {
    int i = blockIdx.x * blockDim.x + threadIdx.x;
    if (i < NN) {
        int o = g_offp[i] + g_bsumex[i / SCAN_BLK];
        g_off[i] = o;
        g_cursor[i] = o;
    }
}

// ================= CSR positional scatter =================
__global__ void k_edge_pos(const int* __restrict__ src, const int* __restrict__ dst) {
    int e = blockIdx.x * blockDim.x + threadIdx.x;
    if (e < NE) {
        int pos = atomicAdd(&g_cursor[dst[e]], 1);
        g_csrc[pos] = src[e];
    }
}

// ================= GEMM1: hs = half(x @ W1 * dinv[row]) =================
#define XS_F4 (256 * 17)
#define GEMM1_SMEM (XS_F4 * 16 + 64 * 64 * 4)   // 86016 B

__global__ void __launch_bounds__(256, 2) k_gemm1(const float* __restrict__ x,
                                                  const float* __restrict__ W1) {
    extern __shared__ float4 sm4[];
    float4* xs4 = sm4;                     // [256][17]
    float*  Ws  = (float*)(sm4 + XS_F4);   // [64][64]

    const int tid = threadIdx.x;
    const int c  = tid & 7;
    const int rg = tid >> 3;
    const int row_base = blockIdx.x * 256;

    u64 acc[8][4];
#pragma unroll
    for (int i = 0; i < 8; i++)
#pragma unroll
        for (int p = 0; p < 4; p++) acc[i][p] = 0ull;

    const float4* x4  = reinterpret_cast<const float4*>(x);
    const float4* W14 = reinterpret_cast<const float4*>(W1);
    float4* Ws4 = reinterpret_cast<float4*>(Ws);

    for (int kc = 0; kc < 2; kc++) {
#pragma unroll
        for (int j = 0; j < 16; j++) {
            int f = tid + 256 * j;
            int row = f >> 4;
            int kq  = f & 15;
            int grow = min(row_base + row, NN - 1);
            xs4[row * 17 + kq] = x4[(size_t)grow * 32 + kc * 16 + kq];
        }
#pragma unroll
        for (int j = 0; j < 4; j++) {
            int f = tid + 256 * j;
            Ws4[f] = W14[kc * 1024 + f];
        }
        __syncthreads();

#define ROWSTEP(i, comp)                                   \
        {                                                  \
            u64 xd = dup2(xq[i].comp);                     \
            ffma2(acc[i][0], xd, wA.x);                    \
            ffma2(acc[i][1], xd, wA.y);                    \
            ffma2(acc[i][2], xd, wB.x);                    \
            ffma2(acc[i][3], xd, wB.y);                    \
        }
#define KSTEP(comp, kk)                                                        \
        {                                                                      \
            const ulonglong2* wr =                                             \
                (const ulonglong2*)(Ws + (k4 * 4 + kk) * 64 + c * 8);          \
            ulonglong2 wA = wr[0];                                             \
            ulonglong2 wB = wr[1];                                             \
            ROWSTEP(0, comp) ROWSTEP(1, comp) ROWSTEP(2, comp) ROWSTEP(3, comp)\
            ROWSTEP(4, comp) ROWSTEP(5, comp) ROWSTEP(6, comp) ROWSTEP(7, comp)\
        }

#pragma unroll 4
        for (int k4 = 0; k4 < 16; k4++) {
            float4 xq[8];
#pragma unroll
            for (int i = 0; i < 8; i++) xq[i] = xs4[(rg + 32 * i) * 17 + k4];
            KSTEP(x, 0)
            KSTEP(y, 1)
            KSTEP(z, 2)
            KSTEP(w, 3)
        }
        __syncthreads();
    }

    // epilogue: scale by dinv, convert to fp16, 16B store per thread
    uint4* hs16 = reinterpret_cast<uint4*>(g_hs);
#pragma unroll
    for (int i = 0; i < 8; i++) {
        int grow = row_base + rg + 32 * i;
        if (grow < NN) {
            float di = g_dinv[grow];
            float2 p0 = unpack2(acc[i][0]);
            float2 p1 = unpack2(acc[i][1]);
            float2 p2 = unpack2(acc[i][2]);
            float2 p3 = unpack2(acc[i][3]);
            __half2 h0 = __float22half2_rn(make_float2(p0.x * di, p0.y * di));
            __half2 h1 = __float22half2_rn(make_float2(p1.x * di, p1.y * di));
            __half2 h2 = __float22half2_rn(make_float2(p2.x * di, p2.y * di));
            __half2 h3 = __float22half2_rn(make_float2(p3.x * di, p3.y * di));
            uint4 u;
            u.x = h2_bits(h0);
            u.y = h2_bits(h1);
            u.z = h2_bits(h2);
            u.w = h2_bits(h3);
            hs16[(size_t)grow * 8 + c] = u;   // row = 8 uint4 (128B)
        }
    }
#undef KSTEP
#undef ROWSTEP
}

// ================= agg1: warp-per-node gather-sum (fp16 rows, fp32 acc) ======
__global__ void __launch_bounds__(256) k_agg1(const float* __restrict__ b1) {
    int wg = (blockIdx.x * blockDim.x + threadIdx.x) >> 5;
    if (wg >= NN) return;
    const int d = wg;
    const int lane = threadIdx.x & 31;

    const __half2* hs2 = reinterpret_cast<const __half2*>(g_hs);
    float2 acc = __half22float2(hs2[(size_t)d * 32 + lane]);

    const int beg = g_off[d];
    const int cnt = g_indeg[d];
    for (int base = 0; base < cnt; base += 32) {
        int rem = cnt - base;
        int take = rem < 32 ? rem : 32;
        int s = 0;
        if (lane < take) s = g_csrc[beg + base + lane];
#pragma unroll 4
        for (int j = 0; j < take; j++) {
            int sj = __shfl_sync(0xffffffffu, s, j);
            float2 v = __half22float2(hs2[(size_t)sj * 32 + lane]);
            acc.x += v.x;
            acc.y += v.y;
        }
    }

    float di = g_dinv[d];
    float2 b = reinterpret_cast<const float2*>(b1)[lane];
    float2 o;
    o.x = fmaxf(fmaf(acc.x, di, b.x), 0.0f);
    o.y = fmaxf(fmaf(acc.y, di, b.y), 0.0f);
    reinterpret_cast<float2*>(g_agg)[(size_t)d * 32 + lane] = o;
}

// ================= GEMM2: h2s = (agg @ W2) * dinv[row], stride-16 padded ======
__global__ void __launch_bounds__(256) k_gemm2(const float* __restrict__ W2) {
    __shared__ float Ws[FH * FO];
    for (int i = threadIdx.x; i < FH * FO; i += blockDim.x) Ws[i] = W2[i];
    __syncthreads();

    int n = blockIdx.x * blockDim.x + threadIdx.x;
    if (n >= NN) return;

    float acc[FO];
#pragma unroll
    for (int j = 0; j < FO; j++) acc[j] = 0.0f;

    const float4* a4 = reinterpret_cast<const float4*>(g_agg + (size_t)n * FH);
#pragma unroll
    for (int k4 = 0; k4 < 16; k4++) {
        float4 a = a4[k4];
        float av[4] = {a.x, a.y, a.z, a.w};
#pragma unroll
        for (int kk = 0; kk < 4; kk++) {
            int k = k4 * 4 + kk;
#pragma unroll
            for (int j = 0; j < FO; j++) acc[j] = fmaf(av[kk], Ws[k * FO + j], acc[j]);
        }
    }

    float di = g_dinv[n];
    float2* o2 = reinterpret_cast<float2*>(g_h2s + (size_t)n * 16);
#pragma unroll
    for (int p = 0; p < 5; p++)
        o2[p] = make_float2(acc[p * 2] * di, acc[p * 2 + 1] * di);
}

// ================= agg2: warp-per-node gather-sum (10 features) =================
__global__ void __launch_bounds__(256) k_agg2(const float* __restrict__ b2,
                                              float* __restrict__ out) {
    int wg = (blockIdx.x * blockDim.x + threadIdx.x) >> 5;
    if (wg >= NN) return;
    const int d = wg;
    const int lane = threadIdx.x & 31;

    float acc = 0.0f;
    if (lane < FO) acc = g_h2s[(size_t)d * 16 + lane];

    const int beg = g_off[d];
    const int cnt = g_indeg[d];
    for (int base = 0; base < cnt; base += 32) {
        int rem = cnt - base;
        int take = rem < 32 ? rem : 32;
        int s = 0;
        if (lane < take) s = g_csrc[beg + base + lane];
#pragma unroll 4
        for (int j = 0; j < take; j++) {
            int sj = __shfl_sync(0xffffffffu, s, j);
            if (lane < FO) acc += g_h2s[(size_t)sj * 16 + lane];
        }
    }

    if (lane < FO) {
        float di = g_dinv[d];
        out[(size_t)d * FO + lane] = fmaf(acc, di, b2[lane]);
    }
}

extern "C" void kernel_launch(void* const* d_in, const int* in_sizes, int n_in,
                              void* d_out, int out_size) {
    const float* x  = (const float*)d_in[0];
    const int*   ei = (const int*)d_in[1];
    const float* W1 = (const float*)d_in[2];
    const float* b1 = (const float*)d_in[3];
    const float* W2 = (const float*)d_in[4];
    const float* b2 = (const float*)d_in[5];
    float* out = (float*)d_out;

    const int* src = ei;
    const int* dst = ei + NE;

    static bool attr_set = false;
    if (!attr_set) {
        cudaFuncSetAttribute(k_gemm1, cudaFuncAttributeMaxDynamicSharedMemorySize,
                             GEMM1_SMEM);
        attr_set = true;
    }

    k_zero<<<(NN + 255) / 256, 256>>>();
    k_indeg<<<(NE + 255) / 256, 256>>>(dst);
    k_scan1<<<NSCAN, SCAN_BLK>>>();
    k_scan2<<<1, 256>>>();
    k_scan3<<<(NN + 255) / 256, 256>>>();
    k_edge_pos<<<(NE + 255) / 256, 256>>>(src, dst);
    k_gemm1<<<(NN + 255) / 256, 256, GEMM1_SMEM>>>(x, W1);
    k_agg1<<<(NN * 32 + 255) / 256, 256>>>(b1);
    k_gemm2<<<(NN + 255) / 256, 256>>>(W2);
    k_agg2<<<(NN * 32 + 255) / 256, 256>>>(b2, out);
}